// round 11
// baseline (speedup 1.0000x reference)
#include <cuda_runtime.h>

#define NB      512
#define NL      512
#define NC      8
#define NCHK    16        // chunks per batch
#define STEPS   32        // increments per chunk (last: 31 real + 1 zero)
#define CSTRIDE 264       // floats per chunk in staging (32*8 + 8 pad)
#define SIGSZ   584       // 8 + 64 + 512
#define S2OFF   8
#define S3OFF   72

typedef unsigned long long ull;

__device__ __forceinline__ void ffma2(ull& d, ull a, ull b) {
    asm("fma.rn.f32x2 %0, %1, %2, %0;" : "+l"(d) : "l"(a), "l"(b));
}
__device__ __forceinline__ ull fma2n(ull a, ull b, ull c) {
    ull r; asm("fma.rn.f32x2 %0, %1, %2, %3;" : "=l"(r) : "l"(a), "l"(b), "l"(c)); return r;
}
__device__ __forceinline__ ull dup2(float x) {
    ull r; asm("mov.b64 %0, {%1, %1};" : "=l"(r) : "f"(x)); return r;
}
__device__ __forceinline__ void unpk2(ull v, float& lo, float& hi) {
    asm("mov.b64 {%0, %1}, %2;" : "=f"(lo), "=f"(hi) : "l"(v));
}

// ---------------------------------------------------------------------------
// One block = one batch. 256 threads = 16 chunks x 16 threads.
// Thread (g, h): i = h&7, chalf = h>>3, c0 = 4*chalf. Owns:
//   S1[i] (redundant across chalf), S2[i, c0..c0+3] (2 x f32x2),
//   S3[i, c0+cl, :] for cl=0..3 (4 c x 4 d-pairs of f32x2).
// Per step (OLD state on RHS):
//   coef[i,c] = S2[i,c] + dx[c]*(S1[i]/2 + dxi/6)
//   S3[i,c,d] += coef * dx[d]
//   S2[i,c]   += dx[c]*(S1[i] + dxi/2)
//   S1[i]     += dxi
// Owned c-slice dx[c0..c0+3] comes from lo/hi via 64-bit selects (no extra
// LDS). Next row is prefetched (double buffer) to hide LDS latency.
// ---------------------------------------------------------------------------
__global__ __launch_bounds__(256, 4) void sig_fused_kernel(
    const float* __restrict__ path, float* __restrict__ out)
{
    const int b     = blockIdx.x;
    const int t     = threadIdx.x;     // 0..255
    const int g     = t >> 4;          // chunk 0..15
    const int h     = t & 15;
    const int i     = h & 7;           // level-1 row
    const int chalf = h >> 3;
    const int c0    = chalf * 4;       // owned c-range start

    // Union: staging (16*264 = 4224 fl) reused as segment sigs (16*584 fl).
    __shared__ __align__(16) float smem_u[NCHK * SIGSZ];   // 37376 B
    float* sinc = smem_u;
    float* sseg = smem_u;

    const float* prow = path + (size_t)b * NL * NC;

    // ---- Stage increments (chunk-padded layout; zero row for the tail) ----
    for (int r = t; r < NCHK * STEPS; r += 256) {
        float* w = sinc + (r >> 5) * CSTRIDE + (r & 31) * NC;
        if (r < NL - 1) {
            const float4* p = (const float4*)(prow + r * NC);
            float4 a0 = p[0], a1 = p[1], b0 = p[2], b1 = p[3];
            ((float4*)w)[0] = make_float4(b0.x - a0.x, b0.y - a0.y, b0.z - a0.z, b0.w - a0.w);
            ((float4*)w)[1] = make_float4(b1.x - a1.x, b1.y - a1.y, b1.z - a1.z, b1.w - a1.w);
        } else {
            ((float4*)w)[0] = make_float4(0.f, 0.f, 0.f, 0.f);
            ((float4*)w)[1] = make_float4(0.f, 0.f, 0.f, 0.f);
        }
    }
    __syncthreads();

    float s1 = 0.f;
    ull s2p[2] = {0ull, 0ull};            // S2[i, c0..c0+1], S2[i, c0+2..c0+3]
    ull s3[4][4];                         // s3[cl][dp] = {S3[i,c0+cl,2dp], 2dp+1}
    #pragma unroll
    for (int cl = 0; cl < 4; cl++)
        #pragma unroll
        for (int dp = 0; dp < 4; dp++) s3[cl][dp] = 0ull;

    const float* myc = sinc + g * CSTRIDE;

    // Software-pipelined mainloop: prefetch row s+1 while computing row s.
    ulonglong2 lo = *(const ulonglong2*)myc;        // {dx0,dx1},{dx2,dx3}
    ulonglong2 hi = *(const ulonglong2*)(myc + 4);  // {dx4,dx5},{dx6,dx7}
    float dxi = myc[i];

    #pragma unroll 2
    for (int s = 0; s < STEPS; s++) {
        // branchless prefetch (wraps to row 0 on the last iteration)
        const float* nr = myc + ((s + 1) & (STEPS - 1)) * NC;
        ulonglong2 nlo = *(const ulonglong2*)nr;
        ulonglong2 nhi = *(const ulonglong2*)(nr + 4);
        float ndxi = nr[i];

        // owned c-slice from registers (no LDS)
        ull dca = chalf ? hi.x : lo.x;
        ull dcb = chalf ? hi.y : lo.y;

        float hs = fmaf(dxi, 1.f / 6.f, 0.5f * s1);   // S1/2 + dxi/6
        float gs = fmaf(dxi, 0.5f, s1);               // S1 + dxi/2
        ull h2 = dup2(hs), g2 = dup2(gs);

        ull coef0 = fma2n(h2, dca, s2p[0]);
        ull coef1 = fma2n(h2, dcb, s2p[1]);
        s2p[0]    = fma2n(g2, dca, s2p[0]);
        s2p[1]    = fma2n(g2, dcb, s2p[1]);

        float cf0, cf1, cf2, cf3;
        unpk2(coef0, cf0, cf1);
        unpk2(coef1, cf2, cf3);
        ull cd0 = dup2(cf0), cd1 = dup2(cf1), cd2 = dup2(cf2), cd3 = dup2(cf3);

        ull dx0 = lo.x, dx1 = lo.y, dx2v = hi.x, dx3 = hi.y;
        ffma2(s3[0][0], cd0, dx0); ffma2(s3[0][1], cd0, dx1);
        ffma2(s3[0][2], cd0, dx2v); ffma2(s3[0][3], cd0, dx3);
        ffma2(s3[1][0], cd1, dx0); ffma2(s3[1][1], cd1, dx1);
        ffma2(s3[1][2], cd1, dx2v); ffma2(s3[1][3], cd1, dx3);
        ffma2(s3[2][0], cd2, dx0); ffma2(s3[2][1], cd2, dx1);
        ffma2(s3[2][2], cd2, dx2v); ffma2(s3[2][3], cd2, dx3);
        ffma2(s3[3][0], cd3, dx0); ffma2(s3[3][1], cd3, dx1);
        ffma2(s3[3][2], cd3, dx2v); ffma2(s3[3][3], cd3, dx3);

        s1 += dxi;
        lo = nlo; hi = nhi; dxi = ndxi;
    }
    __syncthreads();   // all staging reads done before sseg overwrites

    // ---- Write segment signature ----
    {
        float* S = sseg + g * SIGSZ;
        if (h < 8) S[h] = s1;                       // chalf==0 writes S1
        *(ull*)(S + S2OFF + i * 8 + c0)     = s2p[0];
        *(ull*)(S + S2OFF + i * 8 + c0 + 2) = s2p[1];
        #pragma unroll
        for (int cl = 0; cl < 4; cl++)
            #pragma unroll
            for (int dp = 0; dp < 4; dp++)
                *(ull*)(S + S3OFF + i * 64 + (c0 + cl) * 8 + 2 * dp) = s3[cl][dp];
    }
    __syncthreads();

    // ---- Chen tree combine: 16 -> 8 -> 4 -> 2 -> 1 (result in sseg[0]) ----
    //   C1 = A1 + B1
    //   C2[i,c]   = A2 + B2 + A1[i]*B1[c]
    //   C3[i,c,d] = A3 + B3 + A1[i]*B2[c,d] + A2[i,c]*B1[d]
    // NOTE: the base loop is required — at st=1 work=512 > 256 threads.
    #pragma unroll
    for (int st = 1; st < NCHK; st <<= 1) {
        const int work = (NCHK / (2 * st)) * 64;
        for (int base = 0; base < work; base += 256) {
            const int w   = base + t;
            const bool act = w < work;
            const int m   = w >> 6;
            const int lt  = w & 63;
            const int i2  = lt >> 3;
            const int c2  = lt & 7;
            float* A = sseg + (size_t)(2 * st * m) * SIGSZ;
            const float* B = sseg + (size_t)(2 * st * m + st) * SIGSZ;

            float na1 = 0.f, na2 = 0.f, na3[8];
            #pragma unroll
            for (int d = 0; d < 8; d++) na3[d] = 0.f;

            if (act) {
                float a1i = A[i2];
                float a2  = A[S2OFF + lt];
                const float4* a3p = (const float4*)(A + S3OFF + lt * 8);
                float4 av0 = a3p[0], av1 = a3p[1];
                float a3l[8] = {av0.x, av0.y, av0.z, av0.w, av1.x, av1.y, av1.z, av1.w};

                const float4* b1p = (const float4*)B;
                float4 bv0 = b1p[0], bv1 = b1p[1];
                float b1l[8] = {bv0.x, bv0.y, bv0.z, bv0.w, bv1.x, bv1.y, bv1.z, bv1.w};

                float b2t = B[S2OFF + lt];
                const float4* b2p = (const float4*)(B + S2OFF + c2 * 8);
                float4 cv0 = b2p[0], cv1 = b2p[1];
                float b2r[8] = {cv0.x, cv0.y, cv0.z, cv0.w, cv1.x, cv1.y, cv1.z, cv1.w};

                const float4* b3p = (const float4*)(B + S3OFF + lt * 8);
                float4 dv0 = b3p[0], dv1 = b3p[1];
                float b3l[8] = {dv0.x, dv0.y, dv0.z, dv0.w, dv1.x, dv1.y, dv1.z, dv1.w};

                #pragma unroll
                for (int d = 0; d < 8; d++)
                    na3[d] = fmaf(a2, b1l[d], fmaf(a1i, b2r[d], a3l[d] + b3l[d]));

                na2 = fmaf(a1i, b1l[c2], a2 + b2t);
                if (lt < 8) na1 = A[lt] + B[lt];
            }
            __syncthreads();   // reads complete before writes
            if (act) {
                if (lt < 8) A[lt] = na1;
                A[S2OFF + lt] = na2;
                float4* o = (float4*)(A + S3OFF + lt * 8);
                o[0] = make_float4(na3[0], na3[1], na3[2], na3[3]);
                o[1] = make_float4(na3[4], na3[5], na3[6], na3[7]);
            }
            __syncthreads();
        }
    }

    // ---- Store final signature (coalesced) ----
    float* o = out + (size_t)b * SIGSZ;
    for (int k = t; k < SIGSZ; k += 256)
        o[k] = sseg[k];
}

extern "C" void kernel_launch(void* const* d_in, const int* in_sizes, int n_in,
                              void* d_out, int out_size) {
    const float* path = (const float*)d_in[0];
    float* out = (float*)d_out;
    sig_fused_kernel<<<NB, 256>>>(path, out);
}

// round 13
// speedup vs baseline: 1.0014x; 1.0014x over previous
#include <cuda_runtime.h>

#define NB      512
#define NL      512
#define NC      8
#define NCHK    16        // chunks per batch
#define STEPS   32        // increments per chunk (last: 31 real + 1 zero)
#define CSTRIDE 264       // floats per chunk in staging (32*8 + 8 pad)
#define SIGSZ   584       // 8 + 64 + 512
#define S2OFF   8
#define S3OFF   72

typedef unsigned long long ull;

__device__ __forceinline__ void ffma2(ull& d, ull a, ull b) {
    asm("fma.rn.f32x2 %0, %1, %2, %0;" : "+l"(d) : "l"(a), "l"(b));
}
__device__ __forceinline__ ull fma2n(ull a, ull b, ull c) {
    ull r; asm("fma.rn.f32x2 %0, %1, %2, %3;" : "=l"(r) : "l"(a), "l"(b), "l"(c)); return r;
}
__device__ __forceinline__ ull dup2(float x) {
    ull r; asm("mov.b64 %0, {%1, %1};" : "=l"(r) : "f"(x)); return r;
}
__device__ __forceinline__ void unpk2(ull v, float& lo, float& hi) {
    asm("mov.b64 {%0, %1}, %2;" : "=f"(lo), "=f"(hi) : "l"(v));
}

// ---------------------------------------------------------------------------
// One block = one batch. 256 threads = 16 chunks x 16 threads.
// Thread (g, h): i = h&7, chalf = h>>3, c0 = 4*chalf. Owns:
//   S1[i] (redundant across chalf), S2[i, c0..c0+3] (2 x f32x2),
//   S3[i, c0+cl, :] for cl=0..3 (4 c x 4 d-pairs of f32x2).
// Per step (OLD state on RHS):
//   coef[i,c] = S2[i,c] + dx[c]*(S1[i]/2 + dxi/6)
//   S3[i,c,d] += coef * dx[d]
//   S2[i,c]   += dx[c]*(S1[i] + dxi/2)
//   S1[i]     += dxi
// Owned c-slice dx[c0..c0+3] comes from lo/hi via 64-bit selects (no extra
// LDS). No explicit prefetch: unroll-4 lets the compiler hoist LDS; saving
// those registers is what buys 4 blocks/SM (one full wave).
// ---------------------------------------------------------------------------
__global__ __launch_bounds__(256, 4) void sig_fused_kernel(
    const float* __restrict__ path, float* __restrict__ out)
{
    const int b     = blockIdx.x;
    const int t     = threadIdx.x;     // 0..255
    const int g     = t >> 4;          // chunk 0..15
    const int h     = t & 15;
    const int i     = h & 7;           // level-1 row
    const int chalf = h >> 3;
    const int c0    = chalf * 4;       // owned c-range start

    // Union: staging (16*264 = 4224 fl) reused as segment sigs (16*584 fl).
    __shared__ __align__(16) float smem_u[NCHK * SIGSZ];   // 37376 B
    float* sinc = smem_u;
    float* sseg = smem_u;

    const float* prow = path + (size_t)b * NL * NC;

    // ---- Stage increments (chunk-padded layout; zero row for the tail) ----
    for (int r = t; r < NCHK * STEPS; r += 256) {
        float* w = sinc + (r >> 5) * CSTRIDE + (r & 31) * NC;
        if (r < NL - 1) {
            const float4* p = (const float4*)(prow + r * NC);
            float4 a0 = p[0], a1 = p[1], b0 = p[2], b1 = p[3];
            ((float4*)w)[0] = make_float4(b0.x - a0.x, b0.y - a0.y, b0.z - a0.z, b0.w - a0.w);
            ((float4*)w)[1] = make_float4(b1.x - a1.x, b1.y - a1.y, b1.z - a1.z, b1.w - a1.w);
        } else {
            ((float4*)w)[0] = make_float4(0.f, 0.f, 0.f, 0.f);
            ((float4*)w)[1] = make_float4(0.f, 0.f, 0.f, 0.f);
        }
    }
    __syncthreads();

    float s1 = 0.f;
    ull s2p[2] = {0ull, 0ull};            // S2[i, c0..c0+1], S2[i, c0+2..c0+3]
    ull s3[4][4];                         // s3[cl][dp] = {S3[i,c0+cl,2dp], 2dp+1}
    #pragma unroll
    for (int cl = 0; cl < 4; cl++)
        #pragma unroll
        for (int dp = 0; dp < 4; dp++) s3[cl][dp] = 0ull;

    const float* myc = sinc + g * CSTRIDE;

    #pragma unroll 4
    for (int s = 0; s < STEPS; s++) {
        const float* row = myc + s * NC;
        ulonglong2 lo = *(const ulonglong2*)row;         // {dx0,dx1},{dx2,dx3}
        ulonglong2 hi = *(const ulonglong2*)(row + 4);   // {dx4,dx5},{dx6,dx7}
        float dxi = row[i];                              // broadcast LDS

        // owned c-slice from registers (no extra LDS)
        ull dca = chalf ? hi.x : lo.x;
        ull dcb = chalf ? hi.y : lo.y;

        float hs = fmaf(dxi, 1.f / 6.f, 0.5f * s1);   // S1/2 + dxi/6
        float gs = fmaf(dxi, 0.5f, s1);               // S1 + dxi/2
        ull h2 = dup2(hs), g2 = dup2(gs);

        ull coef0 = fma2n(h2, dca, s2p[0]);
        ull coef1 = fma2n(h2, dcb, s2p[1]);
        s2p[0]    = fma2n(g2, dca, s2p[0]);
        s2p[1]    = fma2n(g2, dcb, s2p[1]);

        float cf0, cf1, cf2, cf3;
        unpk2(coef0, cf0, cf1);
        unpk2(coef1, cf2, cf3);
        ull cd0 = dup2(cf0), cd1 = dup2(cf1), cd2 = dup2(cf2), cd3 = dup2(cf3);

        ffma2(s3[0][0], cd0, lo.x); ffma2(s3[0][1], cd0, lo.y);
        ffma2(s3[0][2], cd0, hi.x); ffma2(s3[0][3], cd0, hi.y);
        ffma2(s3[1][0], cd1, lo.x); ffma2(s3[1][1], cd1, lo.y);
        ffma2(s3[1][2], cd1, hi.x); ffma2(s3[1][3], cd1, hi.y);
        ffma2(s3[2][0], cd2, lo.x); ffma2(s3[2][1], cd2, lo.y);
        ffma2(s3[2][2], cd2, hi.x); ffma2(s3[2][3], cd2, hi.y);
        ffma2(s3[3][0], cd3, lo.x); ffma2(s3[3][1], cd3, lo.y);
        ffma2(s3[3][2], cd3, hi.x); ffma2(s3[3][3], cd3, hi.y);

        s1 += dxi;
    }
    __syncthreads();   // all staging reads done before sseg overwrites

    // ---- Write segment signature ----
    {
        float* S = sseg + g * SIGSZ;
        if (h < 8) S[h] = s1;                       // chalf==0 writes S1
        *(ull*)(S + S2OFF + i * 8 + c0)     = s2p[0];
        *(ull*)(S + S2OFF + i * 8 + c0 + 2) = s2p[1];
        #pragma unroll
        for (int cl = 0; cl < 4; cl++)
            #pragma unroll
            for (int dp = 0; dp < 4; dp++)
                *(ull*)(S + S3OFF + i * 64 + (c0 + cl) * 8 + 2 * dp) = s3[cl][dp];
    }
    __syncthreads();

    // ---- Chen tree combine: 16 -> 8 -> 4 -> 2 -> 1 (result in sseg[0]) ----
    //   C1 = A1 + B1
    //   C2[i,c]   = A2 + B2 + A1[i]*B1[c]
    //   C3[i,c,d] = A3 + B3 + A1[i]*B2[c,d] + A2[i,c]*B1[d]
    // NOTE: base loop required — at st=1, work=512 > 256 threads.
    #pragma unroll
    for (int st = 1; st < NCHK; st <<= 1) {
        const int work = (NCHK / (2 * st)) * 64;
        for (int base = 0; base < work; base += 256) {
            const int w   = base + t;
            const bool act = w < work;
            const int m   = w >> 6;
            const int lt  = w & 63;
            const int i2  = lt >> 3;
            const int c2  = lt & 7;
            float* A = sseg + (size_t)(2 * st * m) * SIGSZ;
            const float* B = sseg + (size_t)(2 * st * m + st) * SIGSZ;

            float na1 = 0.f, na2 = 0.f, na3[8];
            #pragma unroll
            for (int d = 0; d < 8; d++) na3[d] = 0.f;

            if (act) {
                float a1i = A[i2];
                float a2  = A[S2OFF + lt];
                const float4* a3p = (const float4*)(A + S3OFF + lt * 8);
                float4 av0 = a3p[0], av1 = a3p[1];
                float a3l[8] = {av0.x, av0.y, av0.z, av0.w, av1.x, av1.y, av1.z, av1.w};

                const float4* b1p = (const float4*)B;
                float4 bv0 = b1p[0], bv1 = b1p[1];
                float b1l[8] = {bv0.x, bv0.y, bv0.z, bv0.w, bv1.x, bv1.y, bv1.z, bv1.w};

                float b2t = B[S2OFF + lt];
                const float4* b2p = (const float4*)(B + S2OFF + c2 * 8);
                float4 cv0 = b2p[0], cv1 = b2p[1];
                float b2r[8] = {cv0.x, cv0.y, cv0.z, cv0.w, cv1.x, cv1.y, cv1.z, cv1.w};

                const float4* b3p = (const float4*)(B + S3OFF + lt * 8);
                float4 dv0 = b3p[0], dv1 = b3p[1];
                float b3l[8] = {dv0.x, dv0.y, dv0.z, dv0.w, dv1.x, dv1.y, dv1.z, dv1.w};

                #pragma unroll
                for (int d = 0; d < 8; d++)
                    na3[d] = fmaf(a2, b1l[d], fmaf(a1i, b2r[d], a3l[d] + b3l[d]));

                na2 = fmaf(a1i, b1l[c2], a2 + b2t);
                if (lt < 8) na1 = A[lt] + B[lt];
            }
            __syncthreads();   // reads complete before writes
            if (act) {
                if (lt < 8) A[lt] = na1;
                A[S2OFF + lt] = na2;
                float4* o = (float4*)(A + S3OFF + lt * 8);
                o[0] = make_float4(na3[0], na3[1], na3[2], na3[3]);
                o[1] = make_float4(na3[4], na3[5], na3[6], na3[7]);
            }
            __syncthreads();
        }
    }

    // ---- Store final signature (coalesced) ----
    float* o = out + (size_t)b * SIGSZ;
    for (int k = t; k < SIGSZ; k += 256)
        o[k] = sseg[k];
}

extern "C" void kernel_launch(void* const* d_in, const int* in_sizes, int n_in,
                              void* d_out, int out_size) {
    const float* path = (const float*)d_in[0];
    float* out = (float*)d_out;
    sig_fused_kernel<<<NB, 256>>>(path, out);
}

// round 15
// speedup vs baseline: 1.1252x; 1.1236x over previous
#include <cuda_runtime.h>

#define NB      512
#define NL      512
#define NC      8
#define NCHK    8         // chunks per batch
#define STEPS   64        // increments per chunk (last: 63 real + 1 zero)
#define CSTRIDE 520       // floats per chunk in staging (64*8 + 8 pad)
#define SIGSZ   584       // 8 + 64 + 512
#define S2OFF   8
#define S3OFF   72

typedef unsigned long long ull;

__device__ __forceinline__ void ffma2(ull& d, ull a, ull b) {
    asm("fma.rn.f32x2 %0, %1, %2, %0;" : "+l"(d) : "l"(a), "l"(b));
}
__device__ __forceinline__ ull dup2(float x) {
    ull r; asm("mov.b64 %0, {%1, %1};" : "=l"(r) : "f"(x)); return r;
}

// ---------------------------------------------------------------------------
// One block = one batch. 256 threads = 8 chunks x 32 threads.
// Thread (g, q): i = q&7, cq = q>>3, c0 = 2*cq. Owns:
//   S1[i] (replicated over cq), S2[i,c0], S2[i,c0+1] (scalars),
//   S3[i,c0,0..7] and S3[i,c0+1,0..7] as 4+4 f32x2 over d-pairs.
// Per step (OLD state on RHS):
//   coef[i,c] = S2[i,c] + dx[c]*(S1[i]/2 + dxi/6)
//   S3[i,c,d] += coef * dx[d]
//   S2[i,c]   += dx[c]*(S1[i] + dxi/2)
//   S1[i]     += dxi
// Small per-thread state (~19 regs) is the point: 5 blocks/SM => all 512
// blocks resident in one wave, ~7 warps/SMSP to hide LDS latency.
// ---------------------------------------------------------------------------
__global__ __launch_bounds__(256, 5) void sig_fused_kernel(
    const float* __restrict__ path, float* __restrict__ out)
{
    const int b  = blockIdx.x;
    const int t  = threadIdx.x;     // 0..255
    const int g  = t >> 5;          // chunk 0..7
    const int q  = t & 31;
    const int i  = q & 7;           // level-1 row
    const int c0 = (q >> 3) * 2;    // owned c-pair start

    // Union: staging (8*520 = 4160 fl) reused as segment sigs (8*584 fl).
    __shared__ __align__(16) float smem_u[NCHK * SIGSZ];   // 18688 B
    float* sinc = smem_u;
    float* sseg = smem_u;

    const float* prow = path + (size_t)b * NL * NC;

    // ---- Stage increments (chunk-padded layout; zero row for the tail) ----
    for (int r = t; r < NCHK * STEPS; r += 256) {
        float* w = sinc + (r >> 6) * CSTRIDE + (r & 63) * NC;
        if (r < NL - 1) {
            const float4* p = (const float4*)(prow + r * NC);
            float4 a0 = p[0], a1 = p[1], b0 = p[2], b1 = p[3];
            ((float4*)w)[0] = make_float4(b0.x - a0.x, b0.y - a0.y, b0.z - a0.z, b0.w - a0.w);
            ((float4*)w)[1] = make_float4(b1.x - a1.x, b1.y - a1.y, b1.z - a1.z, b1.w - a1.w);
        } else {
            ((float4*)w)[0] = make_float4(0.f, 0.f, 0.f, 0.f);
            ((float4*)w)[1] = make_float4(0.f, 0.f, 0.f, 0.f);
        }
    }
    __syncthreads();

    float s1 = 0.f, s2a = 0.f, s2b = 0.f;
    ull s3a[4], s3b[4];
    #pragma unroll
    for (int dp = 0; dp < 4; dp++) { s3a[dp] = 0ull; s3b[dp] = 0ull; }

    const float* myc = sinc + g * CSTRIDE;

    // Software pipeline: prefetch row s+1 while computing row s.
    ulonglong2 lo = *(const ulonglong2*)myc;        // {dx0,dx1},{dx2,dx3}
    ulonglong2 hi = *(const ulonglong2*)(myc + 4);  // {dx4,dx5},{dx6,dx7}
    float dxi = myc[i];
    float dcl = myc[c0], dch = myc[c0 + 1];

    #pragma unroll 4
    for (int s = 0; s < STEPS; s++) {
        const float* nr = myc + ((s + 1) & (STEPS - 1)) * NC;   // wraps at end
        ulonglong2 nlo = *(const ulonglong2*)nr;
        ulonglong2 nhi = *(const ulonglong2*)(nr + 4);
        float ndxi = nr[i];
        float ndcl = nr[c0], ndch = nr[c0 + 1];

        float hs = fmaf(dxi, 1.f / 6.f, 0.5f * s1);   // S1/2 + dxi/6
        float gs = fmaf(dxi, 0.5f, s1);               // S1 + dxi/2

        float coef0 = fmaf(hs, dcl, s2a);
        float coef1 = fmaf(hs, dch, s2b);
        s2a = fmaf(gs, dcl, s2a);
        s2b = fmaf(gs, dch, s2b);

        ull cd0 = dup2(coef0), cd1 = dup2(coef1);

        ffma2(s3a[0], cd0, lo.x); ffma2(s3a[1], cd0, lo.y);
        ffma2(s3a[2], cd0, hi.x); ffma2(s3a[3], cd0, hi.y);
        ffma2(s3b[0], cd1, lo.x); ffma2(s3b[1], cd1, lo.y);
        ffma2(s3b[2], cd1, hi.x); ffma2(s3b[3], cd1, hi.y);

        s1 += dxi;
        lo = nlo; hi = nhi; dxi = ndxi; dcl = ndcl; dch = ndch;
    }
    __syncthreads();   // all staging reads done before sseg overwrites

    // ---- Write segment signature ----
    {
        float* S = sseg + g * SIGSZ;
        if (q < 8) S[q] = s1;                       // cq==0 threads have i==q
        S[S2OFF + i * 8 + c0]     = s2a;
        S[S2OFF + i * 8 + c0 + 1] = s2b;
        #pragma unroll
        for (int dp = 0; dp < 4; dp++) {
            *(ull*)(S + S3OFF + i * 64 + c0 * 8 + 2 * dp)       = s3a[dp];
            *(ull*)(S + S3OFF + i * 64 + (c0 + 1) * 8 + 2 * dp) = s3b[dp];
        }
    }
    __syncthreads();

    // ---- Chen tree combine: 8 -> 4 -> 2 -> 1 (result in sseg[0]) ----
    //   C1 = A1 + B1
    //   C2[i,c]   = A2 + B2 + A1[i]*B1[c]
    //   C3[i,c,d] = A3 + B3 + A1[i]*B2[c,d] + A2[i,c]*B1[d]
    #pragma unroll
    for (int st = 1; st < NCHK; st <<= 1) {
        const int work = (NCHK / (2 * st)) * 64;    // 256, 128, 64
        {
            const int w   = t;
            const bool act = w < work;
            const int m   = w >> 6;
            const int lt  = w & 63;
            const int i2  = lt >> 3;
            const int c2  = lt & 7;
            float* A = sseg + (size_t)(2 * st * m) * SIGSZ;
            const float* B = sseg + (size_t)(2 * st * m + st) * SIGSZ;

            float na1 = 0.f, na2 = 0.f, na3[8];
            #pragma unroll
            for (int d = 0; d < 8; d++) na3[d] = 0.f;

            if (act) {
                float a1i = A[i2];
                float a2  = A[S2OFF + lt];
                const float4* a3p = (const float4*)(A + S3OFF + lt * 8);
                float4 av0 = a3p[0], av1 = a3p[1];
                float a3l[8] = {av0.x, av0.y, av0.z, av0.w, av1.x, av1.y, av1.z, av1.w};

                const float4* b1p = (const float4*)B;
                float4 bv0 = b1p[0], bv1 = b1p[1];
                float b1l[8] = {bv0.x, bv0.y, bv0.z, bv0.w, bv1.x, bv1.y, bv1.z, bv1.w};

                float b2t = B[S2OFF + lt];
                const float4* b2p = (const float4*)(B + S2OFF + c2 * 8);
                float4 cv0 = b2p[0], cv1 = b2p[1];
                float b2r[8] = {cv0.x, cv0.y, cv0.z, cv0.w, cv1.x, cv1.y, cv1.z, cv1.w};

                const float4* b3p = (const float4*)(B + S3OFF + lt * 8);
                float4 dv0 = b3p[0], dv1 = b3p[1];
                float b3l[8] = {dv0.x, dv0.y, dv0.z, dv0.w, dv1.x, dv1.y, dv1.z, dv1.w};

                #pragma unroll
                for (int d = 0; d < 8; d++)
                    na3[d] = fmaf(a2, b1l[d], fmaf(a1i, b2r[d], a3l[d] + b3l[d]));

                na2 = fmaf(a1i, b1l[c2], a2 + b2t);
                if (lt < 8) na1 = A[lt] + B[lt];
            }
            __syncthreads();   // reads complete before writes
            if (act) {
                if (lt < 8) A[lt] = na1;
                A[S2OFF + lt] = na2;
                float4* o = (float4*)(A + S3OFF + lt * 8);
                o[0] = make_float4(na3[0], na3[1], na3[2], na3[3]);
                o[1] = make_float4(na3[4], na3[5], na3[6], na3[7]);
            }
            __syncthreads();
        }
    }

    // ---- Store final signature (coalesced) ----
    float* o = out + (size_t)b * SIGSZ;
    for (int k = t; k < SIGSZ; k += 256)
        o[k] = sseg[k];
}

extern "C" void kernel_launch(void* const* d_in, const int* in_sizes, int n_in,
                              void* d_out, int out_size) {
    const float* path = (const float*)d_in[0];
    float* out = (float*)d_out;
    sig_fused_kernel<<<NB, 256>>>(path, out);
}